// round 1
// baseline (speedup 1.0000x reference)
#include <cuda_runtime.h>

// ---------------------------------------------------------------------------
// LinkPredModel: 2-layer GraphSAGE (mean agg) + edge dot product
//   N=100000 nodes, D=H=128, E=3.2M edges, L=200k label pairs
// Pipeline per call (all graph-capturable, no allocs):
//   detect idx dtype -> zero counts -> count deg -> scan (rowptr/cursor/dinv)
//   -> fill CSR -> agg(x) -> fusedGEMM(l1,+leaky) -> agg(h1) -> fusedGEMM(l2)
//   -> edge dot
// ---------------------------------------------------------------------------

#define MAXN 100000
#define MAXE 3200000

__device__ int   g_cnt[MAXN];
__device__ int   g_rowptr[MAXN + 1];
__device__ int   g_cursor[MAXN];
__device__ float g_dinv[MAXN];
__device__ int   g_col[MAXE];
__device__ float g_agg[(long long)MAXN * 128];
__device__ float g_h1 [(long long)MAXN * 128];
__device__ float g_h2 [(long long)MAXN * 128];
__device__ int   g_is64;

// ---- index accessor: tolerate int64 or int32 edge index buffers ----------
__device__ __forceinline__ int eidx(const void* p, long long i, int is64) {
    if (is64) return (int)__ldg(((const long long*)p) + i);
    return __ldg(((const int*)p) + i);
}

// Detect whether index buffer is int64: for int64 nonneg indices, every odd
// 32-bit word (high half) is 0. Probability all-zero for real int32 indices
// over 4096 samples is negligible.
__global__ void k_detect(const void* ei, int slots64) {
    __shared__ int nonzero;
    if (threadIdx.x == 0) nonzero = 0;
    __syncthreads();
    const int* w = (const int*)ei;
    int slots = slots64 < 4096 ? slots64 : 4096;
    int any = 0;
    for (int i = threadIdx.x; i < slots; i += blockDim.x)
        if (w[2 * i + 1] != 0) any = 1;
    if (any) atomicOr(&nonzero, 1);
    __syncthreads();
    if (threadIdx.x == 0) g_is64 = (nonzero == 0) ? 1 : 0;
}

__global__ void k_zero_cnt(int N) {
    int i = blockIdx.x * blockDim.x + threadIdx.x;
    if (i < N) g_cnt[i] = 0;
}

__global__ void k_count(const void* ei, int E) {
    int e = blockIdx.x * blockDim.x + threadIdx.x;
    if (e >= E) return;
    int is64 = g_is64;
    int d = eidx(ei, (long long)E + e, is64);
    atomicAdd(&g_cnt[d], 1);
}

// Single-block exclusive scan over counts -> rowptr, cursor copy, inv-degree.
__global__ void k_scan(int N) {
    __shared__ int s[1024];
    int tid = threadIdx.x;
    int chunk = (N + 1023) >> 10;
    int beg = tid * chunk;
    int end = beg + chunk; if (end > N) end = N;
    if (beg > N) beg = N;

    int sum = 0;
    for (int i = beg; i < end; i++) sum += g_cnt[i];
    s[tid] = sum;
    __syncthreads();
    // Hillis-Steele inclusive scan
    for (int off = 1; off < 1024; off <<= 1) {
        int v = (tid >= off) ? s[tid - off] : 0;
        __syncthreads();
        s[tid] += v;
        __syncthreads();
    }
    int run = s[tid] - sum;   // exclusive prefix for this thread's chunk
    for (int i = beg; i < end; i++) {
        int c = g_cnt[i];
        g_rowptr[i] = run;
        g_cursor[i] = run;
        g_dinv[i]   = 1.0f / (float)(c > 1 ? c : 1);
        run += c;
    }
    if (tid == 0) g_rowptr[N] = s[1023];
}

__global__ void k_fill(const void* ei, int E) {
    int e = blockIdx.x * blockDim.x + threadIdx.x;
    if (e >= E) return;
    int is64 = g_is64;
    int src = eidx(ei, e, is64);
    int dst = eidx(ei, (long long)E + e, is64);
    int pos = atomicAdd(&g_cursor[dst], 1);
    g_col[pos] = src;
}

// Mean aggregation: one warp per destination node, float4 per lane (128 f32).
__global__ void k_agg(const float* __restrict__ hin, float* __restrict__ out, int N) {
    int warp = (blockIdx.x * blockDim.x + threadIdx.x) >> 5;
    int lane = threadIdx.x & 31;
    if (warp >= N) return;
    int beg = g_rowptr[warp];
    int end = g_rowptr[warp + 1];
    const float4* h4 = (const float4*)hin;
    float4 acc = make_float4(0.f, 0.f, 0.f, 0.f);
    for (int j = beg; j < end; j++) {
        int s = __ldg(&g_col[j]);
        float4 v = __ldg(&h4[(long long)s * 32 + lane]);
        acc.x += v.x; acc.y += v.y; acc.z += v.z; acc.w += v.w;
    }
    float dv = g_dinv[warp];
    acc.x *= dv; acc.y *= dv; acc.z *= dv; acc.w *= dv;
    ((float4*)out)[(long long)warp * 32 + lane] = acc;
}

// Fused SAGE transform: out[n] = A[n]@Wl + X[n]@Wr + b  (+ optional leaky relu)
// Block: 256 threads, 64 rows x 128 cols tile. Thread: 8 rows x 4 cols.
__global__ void __launch_bounds__(256)
k_sage_gemm(const float* __restrict__ A, const float* __restrict__ X,
            const float* __restrict__ Wl, const float* __restrict__ Wr,
            const float* __restrict__ bias, float* __restrict__ out,
            int N, int leaky) {
    __shared__ float sA[64][128];
    __shared__ float sX[64][128];
    int tid = threadIdx.x;
    long long row0 = (long long)blockIdx.x * 64;

    // Load 64x128 tiles of A and X (float4, coalesced)
#pragma unroll
    for (int i = 0; i < 8; i++) {
        int f = tid + i * 256;          // float4 slot within tile (2048 total)
        int r = f >> 5;
        int c4 = f & 31;
        long long grow = row0 + r;
        float4 va = make_float4(0.f, 0.f, 0.f, 0.f);
        float4 vx = va;
        if (grow < N) {
            va = __ldg((const float4*)A + grow * 32 + c4);
            vx = __ldg((const float4*)X + grow * 32 + c4);
        }
        ((float4*)&sA[r][0])[c4] = va;
        ((float4*)&sX[r][0])[c4] = vx;
    }
    __syncthreads();

    int lane = tid & 31;
    int w = tid >> 5;
    int c0 = lane * 4;
    int rb = w * 8;

    float acc[8][4];
#pragma unroll
    for (int r = 0; r < 8; r++)
#pragma unroll
        for (int c = 0; c < 4; c++) acc[r][c] = 0.f;

#pragma unroll 1
    for (int k = 0; k < 128; k += 4) {
        float4 wl[4], wr[4];
#pragma unroll
        for (int kk = 0; kk < 4; kk++) {
            wl[kk] = __ldg((const float4*)(Wl + (k + kk) * 128 + c0));
            wr[kk] = __ldg((const float4*)(Wr + (k + kk) * 128 + c0));
        }
#pragma unroll
        for (int r = 0; r < 8; r++) {
            float4 a4 = *(const float4*)&sA[rb + r][k];
            float4 x4 = *(const float4*)&sX[rb + r][k];
            // kk = 0
            acc[r][0] += a4.x * wl[0].x + x4.x * wr[0].x;
            acc[r][1] += a4.x * wl[0].y + x4.x * wr[0].y;
            acc[r][2] += a4.x * wl[0].z + x4.x * wr[0].z;
            acc[r][3] += a4.x * wl[0].w + x4.x * wr[0].w;
            // kk = 1
            acc[r][0] += a4.y * wl[1].x + x4.y * wr[1].x;
            acc[r][1] += a4.y * wl[1].y + x4.y * wr[1].y;
            acc[r][2] += a4.y * wl[1].z + x4.y * wr[1].z;
            acc[r][3] += a4.y * wl[1].w + x4.y * wr[1].w;
            // kk = 2
            acc[r][0] += a4.z * wl[2].x + x4.z * wr[2].x;
            acc[r][1] += a4.z * wl[2].y + x4.z * wr[2].y;
            acc[r][2] += a4.z * wl[2].z + x4.z * wr[2].z;
            acc[r][3] += a4.z * wl[2].w + x4.z * wr[2].w;
            // kk = 3
            acc[r][0] += a4.w * wl[3].x + x4.w * wr[3].x;
            acc[r][1] += a4.w * wl[3].y + x4.w * wr[3].y;
            acc[r][2] += a4.w * wl[3].z + x4.w * wr[3].z;
            acc[r][3] += a4.w * wl[3].w + x4.w * wr[3].w;
        }
    }

    float4 bb = __ldg((const float4*)bias + lane);
#pragma unroll
    for (int r = 0; r < 8; r++) {
        long long grow = row0 + rb + r;
        if (grow >= N) continue;
        float4 o;
        o.x = acc[r][0] + bb.x;
        o.y = acc[r][1] + bb.y;
        o.z = acc[r][2] + bb.z;
        o.w = acc[r][3] + bb.w;
        if (leaky) {
            o.x = o.x >= 0.f ? o.x : 0.2f * o.x;
            o.y = o.y >= 0.f ? o.y : 0.2f * o.y;
            o.z = o.z >= 0.f ? o.z : 0.2f * o.z;
            o.w = o.w >= 0.f ? o.w : 0.2f * o.w;
        }
        ((float4*)out)[grow * 32 + lane] = o;
    }
}

// Link prediction: out[l] = dot(h2[a], h2[b]); one warp per label edge.
__global__ void k_dot(const float* __restrict__ h, const void* __restrict__ eli,
                      float* __restrict__ out, int L) {
    int warp = (blockIdx.x * blockDim.x + threadIdx.x) >> 5;
    int lane = threadIdx.x & 31;
    if (warp >= L) return;
    int is64 = g_is64;
    int a = eidx(eli, warp, is64);
    int b = eidx(eli, (long long)L + warp, is64);
    const float4* h4 = (const float4*)h;
    float4 va = __ldg(&h4[(long long)a * 32 + lane]);
    float4 vb = __ldg(&h4[(long long)b * 32 + lane]);
    float s = va.x * vb.x + va.y * vb.y + va.z * vb.z + va.w * vb.w;
#pragma unroll
    for (int o = 16; o; o >>= 1) s += __shfl_xor_sync(0xFFFFFFFFu, s, o);
    if (lane == 0) out[warp] = s;
}

extern "C" void kernel_launch(void* const* d_in, const int* in_sizes, int n_in,
                              void* d_out, int out_size) {
    const float* x   = (const float*)d_in[0];
    const void*  ei  = d_in[1];
    const void*  eli = d_in[2];
    const float* W1l = (const float*)d_in[3];
    const float* b1  = (const float*)d_in[4];
    const float* W1r = (const float*)d_in[5];
    const float* W2l = (const float*)d_in[6];
    const float* b2  = (const float*)d_in[7];
    const float* W2r = (const float*)d_in[8];
    float* out = (float*)d_out;

    int N = in_sizes[0] / 128;
    int E = in_sizes[1] / 2;
    int L = in_sizes[2] / 2;

    float *agg, *h1, *h2;
    cudaGetSymbolAddress((void**)&agg, g_agg);
    cudaGetSymbolAddress((void**)&h1,  g_h1);
    cudaGetSymbolAddress((void**)&h2,  g_h2);

    // CSR build
    k_detect<<<1, 256>>>(ei, E);  // E int64-slot samples available either way
    k_zero_cnt<<<(N + 255) / 256, 256>>>(N);
    k_count<<<(E + 255) / 256, 256>>>(ei, E);
    k_scan<<<1, 1024>>>(N);
    k_fill<<<(E + 255) / 256, 256>>>(ei, E);

    int aggBlocks = (N + 7) / 8;          // 8 warps/block
    int gemmBlocks = (N + 63) / 64;

    // Layer 1
    k_agg<<<aggBlocks, 256>>>(x, agg, N);
    k_sage_gemm<<<gemmBlocks, 256>>>(agg, x, W1l, W1r, b1, h1, N, 1);
    // Layer 2
    k_agg<<<aggBlocks, 256>>>(h1, agg, N);
    k_sage_gemm<<<gemmBlocks, 256>>>(agg, h1, W2l, W2r, b2, h2, N, 0);
    // Edge dot
    k_dot<<<(L + 7) / 8, 256>>>(h2, eli, out, L);
}

// round 2
// speedup vs baseline: 1.0917x; 1.0917x over previous
#include <cuda_runtime.h>

// ---------------------------------------------------------------------------
// LinkPredModel: 2-layer GraphSAGE (mean agg) + edge dot product
// R2: parallel scan (was 217us single-block), f32x2-packed GEMM, unrolled agg
// ---------------------------------------------------------------------------

#define MAXN 100000
#define MAXE 3200000

__device__ int   g_cnt[MAXN];
__device__ int   g_rowptr[MAXN + 1];
__device__ int   g_cursor[MAXN];
__device__ float g_dinv[MAXN];
__device__ int   g_col[MAXE];
__device__ float g_agg[(long long)MAXN * 128];
__device__ float g_h1 [(long long)MAXN * 128];
__device__ float g_h2 [(long long)MAXN * 128];
__device__ int   g_is64;
__device__ int   g_bsum[64];
__device__ int   g_boff[64];
// Duplicated weights: Wd[k][c] = (w, w) packed in 64 bits
__device__ unsigned long long g_w1ld[16384];
__device__ unsigned long long g_w1rd[16384];
__device__ unsigned long long g_w2ld[16384];
__device__ unsigned long long g_w2rd[16384];

#define FMA2(acc, a, b) \
    asm("fma.rn.f32x2 %0, %1, %2, %0;" : "+l"(acc) : "l"(a), "l"(b))
#define UNPACK2(lo, hi, v) \
    asm("mov.b64 {%0, %1}, %2;" : "=r"(lo), "=r"(hi) : "l"(v))

// ---- index accessor: tolerate int64 or int32 edge index buffers ----------
__device__ __forceinline__ int eidx(const void* p, long long i, int is64) {
    if (is64) return (int)__ldg(((const long long*)p) + i);
    return __ldg(((const int*)p) + i);
}

__global__ void k_detect(const void* ei, int slots64) {
    __shared__ int nonzero;
    if (threadIdx.x == 0) nonzero = 0;
    __syncthreads();
    const int* w = (const int*)ei;
    int slots = slots64 < 4096 ? slots64 : 4096;
    int any = 0;
    for (int i = threadIdx.x; i < slots; i += blockDim.x)
        if (w[2 * i + 1] != 0) any = 1;
    if (any) atomicOr(&nonzero, 1);
    __syncthreads();
    if (threadIdx.x == 0) g_is64 = (nonzero == 0) ? 1 : 0;
}

__global__ void k_zero_cnt(int N) {
    int i = blockIdx.x * blockDim.x + threadIdx.x;
    if (i < N) g_cnt[i] = 0;
}

__global__ void k_count(const void* ei, int E) {
    int e = blockIdx.x * blockDim.x + threadIdx.x;
    if (e >= E) return;
    int is64 = g_is64;
    int d = eidx(ei, (long long)E + e, is64);
    atomicAdd(&g_cnt[d], 1);
}

// ---- parallel exclusive scan over g_cnt: 3 small kernels ------------------
// scan1: each block scans a 2048-elem chunk locally, writes local prefixes
// into g_rowptr and its chunk total into g_bsum.
__global__ void k_scan1(int N) {
    __shared__ int s[256];
    int b = blockIdx.x, t = threadIdx.x;
    int base = b * 2048 + t * 8;
    int v[8];
    int sum = 0;
#pragma unroll
    for (int j = 0; j < 8; j++) {
        int i = base + j;
        v[j] = (i < N) ? g_cnt[i] : 0;
        sum += v[j];
    }
    s[t] = sum;
    __syncthreads();
    for (int off = 1; off < 256; off <<= 1) {
        int x = (t >= off) ? s[t - off] : 0;
        __syncthreads();
        s[t] += x;
        __syncthreads();
    }
    int ex = s[t] - sum;
#pragma unroll
    for (int j = 0; j < 8; j++) {
        int i = base + j;
        if (i < N) g_rowptr[i] = ex;
        ex += v[j];
    }
    if (t == 255) g_bsum[b] = s[255];
}

// scan2: one block scans the (<=64) block sums.
__global__ void k_scan2(int nb, int N) {
    __shared__ int s[64];
    int t = threadIdx.x;
    int v = (t < nb) ? g_bsum[t] : 0;
    s[t] = v;
    __syncthreads();
    for (int off = 1; off < 64; off <<= 1) {
        int x = (t >= off) ? s[t - off] : 0;
        __syncthreads();
        s[t] += x;
        __syncthreads();
    }
    if (t < nb) g_boff[t] = s[t] - v;
    if (t == 63) g_rowptr[N] = s[63];
}

// scan3: add block offsets; produce rowptr/cursor/dinv.
__global__ void k_scan3(int N) {
    int i = blockIdx.x * blockDim.x + threadIdx.x;
    if (i >= N) return;
    int rp = g_rowptr[i] + g_boff[i >> 11];
    g_rowptr[i] = rp;
    g_cursor[i] = rp;
    int c = g_cnt[i];
    g_dinv[i] = 1.0f / (float)(c > 1 ? c : 1);
}

__global__ void k_fill(const void* ei, int E) {
    int e = blockIdx.x * blockDim.x + threadIdx.x;
    if (e >= E) return;
    int is64 = g_is64;
    int src = eidx(ei, e, is64);
    int dst = eidx(ei, (long long)E + e, is64);
    int pos = atomicAdd(&g_cursor[dst], 1);
    g_col[pos] = src;
}

// Duplicate the 4 weight matrices into (w,w) 64-bit pairs.
__global__ void k_wdup(const float* __restrict__ W1l, const float* __restrict__ W1r,
                       const float* __restrict__ W2l, const float* __restrict__ W2r) {
    int i = blockIdx.x * blockDim.x + threadIdx.x;
    if (i >= 16384) return;
    unsigned int a = __float_as_uint(__ldg(W1l + i));
    unsigned int b = __float_as_uint(__ldg(W1r + i));
    unsigned int c = __float_as_uint(__ldg(W2l + i));
    unsigned int d = __float_as_uint(__ldg(W2r + i));
    g_w1ld[i] = (unsigned long long)a | ((unsigned long long)a << 32);
    g_w1rd[i] = (unsigned long long)b | ((unsigned long long)b << 32);
    g_w2ld[i] = (unsigned long long)c | ((unsigned long long)c << 32);
    g_w2rd[i] = (unsigned long long)d | ((unsigned long long)d << 32);
}

// Mean aggregation: one warp per node, float4 per lane, edge loop x4 unrolled.
__global__ void k_agg(const float* __restrict__ hin, float* __restrict__ out, int N) {
    int warp = (blockIdx.x * blockDim.x + threadIdx.x) >> 5;
    int lane = threadIdx.x & 31;
    if (warp >= N) return;
    int beg = g_rowptr[warp];
    int end = g_rowptr[warp + 1];
    const float4* h4 = (const float4*)hin;
    float4 a0 = make_float4(0.f, 0.f, 0.f, 0.f);
    float4 a1 = a0;
    int j = beg;
    for (; j + 3 < end; j += 4) {
        int s0 = __ldg(&g_col[j]);
        int s1 = __ldg(&g_col[j + 1]);
        int s2 = __ldg(&g_col[j + 2]);
        int s3 = __ldg(&g_col[j + 3]);
        float4 v0 = __ldg(&h4[(long long)s0 * 32 + lane]);
        float4 v1 = __ldg(&h4[(long long)s1 * 32 + lane]);
        float4 v2 = __ldg(&h4[(long long)s2 * 32 + lane]);
        float4 v3 = __ldg(&h4[(long long)s3 * 32 + lane]);
        a0.x += v0.x + v2.x; a0.y += v0.y + v2.y; a0.z += v0.z + v2.z; a0.w += v0.w + v2.w;
        a1.x += v1.x + v3.x; a1.y += v1.y + v3.y; a1.z += v1.z + v3.z; a1.w += v1.w + v3.w;
    }
    for (; j < end; j++) {
        int s = __ldg(&g_col[j]);
        float4 v = __ldg(&h4[(long long)s * 32 + lane]);
        a0.x += v.x; a0.y += v.y; a0.z += v.z; a0.w += v.w;
    }
    float dv = g_dinv[warp];
    float4 o;
    o.x = (a0.x + a1.x) * dv;
    o.y = (a0.y + a1.y) * dv;
    o.z = (a0.z + a1.z) * dv;
    o.w = (a0.w + a1.w) * dv;
    ((float4*)out)[(long long)warp * 32 + lane] = o;
}

// Fused SAGE transform with packed f32x2 FMA:
//   out[n] = A[n]@Wl + X[n]@Wr + b  (+ optional leaky relu)
// Tile: 64 rows x 128 cols. Activations stored k-major in smem so a row-pair
// is one LDS.64; weights come pre-duplicated as (w,w) pairs.
// Thread: 4 row-pairs (8 rows) x 4 cols -> 32 ffma2 per k.
__global__ void __launch_bounds__(256)
k_sage_gemm(const float* __restrict__ A, const float* __restrict__ X,
            const unsigned long long* __restrict__ Wld,
            const unsigned long long* __restrict__ Wrd,
            const float* __restrict__ bias, float* __restrict__ out,
            int N, int leaky) {
    extern __shared__ float smem[];
    float* sA = smem;            // [k=128][row=64]
    float* sX = smem + 8192;
    int tid = threadIdx.x;
    long long row0 = (long long)blockIdx.x * 64;

    // Load + transpose tiles (strided global reads, conflict-free smem writes)
#pragma unroll
    for (int i = 0; i < 8; i++) {
        int f = tid + i * 256;       // 2048 float4 slots
        int row = f & 63;
        int kq  = f >> 6;            // 0..31 (quad of k)
        long long grow = row0 + row;
        float4 va = make_float4(0.f, 0.f, 0.f, 0.f);
        float4 vx = va;
        if (grow < N) {
            va = __ldg((const float4*)A + grow * 32 + kq);
            vx = __ldg((const float4*)X + grow * 32 + kq);
        }
        int k0 = kq * 4;
        sA[(k0 + 0) * 64 + row] = va.x;
        sA[(k0 + 1) * 64 + row] = va.y;
        sA[(k0 + 2) * 64 + row] = va.z;
        sA[(k0 + 3) * 64 + row] = va.w;
        sX[(k0 + 0) * 64 + row] = vx.x;
        sX[(k0 + 1) * 64 + row] = vx.y;
        sX[(k0 + 2) * 64 + row] = vx.z;
        sX[(k0 + 3) * 64 + row] = vx.w;
    }
    __syncthreads();

    int lane = tid & 31;
    int w = tid >> 5;
    int c0 = lane * 4;     // column base (4 cols per thread)
    int rb2 = w * 4;       // row-pair base (4 pairs = 8 rows per warp's thread)

    unsigned long long acc[4][4];
#pragma unroll
    for (int rp = 0; rp < 4; rp++)
#pragma unroll
        for (int c = 0; c < 4; c++) acc[rp][c] = 0ull;

#pragma unroll 2
    for (int k = 0; k < 128; k++) {
        const unsigned long long* sa = (const unsigned long long*)(sA + k * 64);
        const unsigned long long* sx = (const unsigned long long*)(sX + k * 64);
        ulonglong2 l0 = __ldg((const ulonglong2*)(Wld + k * 128 + c0));
        ulonglong2 l1 = __ldg((const ulonglong2*)(Wld + k * 128 + c0 + 2));
        ulonglong2 r0 = __ldg((const ulonglong2*)(Wrd + k * 128 + c0));
        ulonglong2 r1 = __ldg((const ulonglong2*)(Wrd + k * 128 + c0 + 2));
#pragma unroll
        for (int rp = 0; rp < 4; rp++) {
            unsigned long long a2 = sa[rb2 + rp];
            unsigned long long x2 = sx[rb2 + rp];
            FMA2(acc[rp][0], a2, l0.x);
            FMA2(acc[rp][1], a2, l0.y);
            FMA2(acc[rp][2], a2, l1.x);
            FMA2(acc[rp][3], a2, l1.y);
            FMA2(acc[rp][0], x2, r0.x);
            FMA2(acc[rp][1], x2, r0.y);
            FMA2(acc[rp][2], x2, r1.x);
            FMA2(acc[rp][3], x2, r1.y);
        }
    }

    float4 bb = __ldg((const float4*)bias + lane);
#pragma unroll
    for (int rp = 0; rp < 4; rp++) {
        unsigned int lo[4], hi[4];
#pragma unroll
        for (int c = 0; c < 4; c++) UNPACK2(lo[c], hi[c], acc[rp][c]);
        long long re = row0 + w * 8 + 2 * rp;   // even row
        float4 oe, oo;
        oe.x = __uint_as_float(lo[0]) + bb.x;
        oe.y = __uint_as_float(lo[1]) + bb.y;
        oe.z = __uint_as_float(lo[2]) + bb.z;
        oe.w = __uint_as_float(lo[3]) + bb.w;
        oo.x = __uint_as_float(hi[0]) + bb.x;
        oo.y = __uint_as_float(hi[1]) + bb.y;
        oo.z = __uint_as_float(hi[2]) + bb.z;
        oo.w = __uint_as_float(hi[3]) + bb.w;
        if (leaky) {
            oe.x = oe.x >= 0.f ? oe.x : 0.2f * oe.x;
            oe.y = oe.y >= 0.f ? oe.y : 0.2f * oe.y;
            oe.z = oe.z >= 0.f ? oe.z : 0.2f * oe.z;
            oe.w = oe.w >= 0.f ? oe.w : 0.2f * oe.w;
            oo.x = oo.x >= 0.f ? oo.x : 0.2f * oo.x;
            oo.y = oo.y >= 0.f ? oo.y : 0.2f * oo.y;
            oo.z = oo.z >= 0.f ? oo.z : 0.2f * oo.z;
            oo.w = oo.w >= 0.f ? oo.w : 0.2f * oo.w;
        }
        if (re < N)     ((float4*)out)[re * 32 + lane] = oe;
        if (re + 1 < N) ((float4*)out)[(re + 1) * 32 + lane] = oo;
    }
}

// Link prediction: out[l] = dot(h2[a], h2[b]); one warp per label edge.
__global__ void k_dot(const float* __restrict__ h, const void* __restrict__ eli,
                      float* __restrict__ out, int L) {
    int warp = (blockIdx.x * blockDim.x + threadIdx.x) >> 5;
    int lane = threadIdx.x & 31;
    if (warp >= L) return;
    int is64 = g_is64;
    int a = eidx(eli, warp, is64);
    int b = eidx(eli, (long long)L + warp, is64);
    const float4* h4 = (const float4*)h;
    float4 va = __ldg(&h4[(long long)a * 32 + lane]);
    float4 vb = __ldg(&h4[(long long)b * 32 + lane]);
    float s = va.x * vb.x + va.y * vb.y + va.z * vb.z + va.w * vb.w;
#pragma unroll
    for (int o = 16; o; o >>= 1) s += __shfl_xor_sync(0xFFFFFFFFu, s, o);
    if (lane == 0) out[warp] = s;
}

extern "C" void kernel_launch(void* const* d_in, const int* in_sizes, int n_in,
                              void* d_out, int out_size) {
    const float* x   = (const float*)d_in[0];
    const void*  ei  = d_in[1];
    const void*  eli = d_in[2];
    const float* W1l = (const float*)d_in[3];
    const float* b1  = (const float*)d_in[4];
    const float* W1r = (const float*)d_in[5];
    const float* W2l = (const float*)d_in[6];
    const float* b2  = (const float*)d_in[7];
    const float* W2r = (const float*)d_in[8];
    float* out = (float*)d_out;

    int N = in_sizes[0] / 128;
    int E = in_sizes[1] / 2;
    int L = in_sizes[2] / 2;

    float *agg, *h1, *h2;
    unsigned long long *w1ld, *w1rd, *w2ld, *w2rd;
    cudaGetSymbolAddress((void**)&agg,  g_agg);
    cudaGetSymbolAddress((void**)&h1,   g_h1);
    cudaGetSymbolAddress((void**)&h2,   g_h2);
    cudaGetSymbolAddress((void**)&w1ld, g_w1ld);
    cudaGetSymbolAddress((void**)&w1rd, g_w1rd);
    cudaGetSymbolAddress((void**)&w2ld, g_w2ld);
    cudaGetSymbolAddress((void**)&w2rd, g_w2rd);

    cudaFuncSetAttribute(k_sage_gemm,
                         cudaFuncAttributeMaxDynamicSharedMemorySize, 65536);

    // CSR build
    k_detect<<<1, 256>>>(ei, E);
    k_zero_cnt<<<(N + 255) / 256, 256>>>(N);
    k_count<<<(E + 255) / 256, 256>>>(ei, E);
    int nb = (N + 2047) / 2048;
    k_scan1<<<nb, 256>>>(N);
    k_scan2<<<1, 64>>>(nb, N);
    k_scan3<<<(N + 255) / 256, 256>>>(N);
    k_fill<<<(E + 255) / 256, 256>>>(ei, E);
    k_wdup<<<64, 256>>>(W1l, W1r, W2l, W2r);

    int aggBlocks = (N + 7) / 8;
    int gemmBlocks = (N + 63) / 64;

    // Layer 1
    k_agg<<<aggBlocks, 256>>>(x, agg, N);
    k_sage_gemm<<<gemmBlocks, 256, 65536>>>(agg, x, w1ld, w1rd, b1, h1, N, 1);
    // Layer 2
    k_agg<<<aggBlocks, 256>>>(h1, agg, N);
    k_sage_gemm<<<gemmBlocks, 256, 65536>>>(agg, h1, w2ld, w2rd, b2, h2, N, 0);
    // Edge dot
    k_dot<<<(L + 7) / 8, 256>>>(h2, eli, out, L);
}

// round 4
// speedup vs baseline: 2.0601x; 1.8871x over previous
#include <cuda_runtime.h>
#include <cstdint>

// ---------------------------------------------------------------------------
// LinkPredModel: 2-layer GraphSAGE (mean agg) + edge dot
// R4: portable tensor cores (mma.sync m16n8k8 tf32) — tcgen05 unavailable
//     (harness compiles for compute_103 virtual arch, no 'a' features).
// fp32 aggregation (precision), tf32 GEMM with fragment-packed operands.
// ---------------------------------------------------------------------------

#define MAXN 100000
#define MAXE 3200000

__device__ int   g_cnt[MAXN];
__device__ int   g_rowptr[MAXN + 1];
__device__ int   g_cursor[MAXN];
__device__ float g_dinv[MAXN];
__device__ int   g_col[MAXE];
__device__ int   g_is64;
__device__ int   g_bsum[64];
__device__ int   g_boff[64];

__device__ __align__(16) float g_agg[(long long)MAXN * 128];
__device__ __align__(16) float g_h1 [(long long)MAXN * 128];
__device__ __align__(16) float g_h2 [(long long)MAXN * 128];
// fragment-packed tf32 weights: [W1l, W1r, W2l, W2r] x 16384 u32 each
__device__ __align__(16) uint32_t g_wtf[4 * 16384];

// ---- index accessor: tolerate int64 or int32 edge index buffers ----------
__device__ __forceinline__ int eidx(const void* p, long long i, int is64) {
    if (is64) return (int)__ldg(((const long long*)p) + i);
    return __ldg(((const int*)p) + i);
}

__device__ __forceinline__ uint32_t f2tf32(float f) {
    uint32_t u;
    asm("cvt.rna.tf32.f32 %0, %1;" : "=r"(u) : "f"(f));
    return u;
}

#define MMA_TF32(d, a, b) \
    asm volatile("mma.sync.aligned.m16n8k8.row.col.f32.tf32.tf32.f32 " \
        "{%0,%1,%2,%3},{%4,%5,%6,%7},{%8,%9},{%0,%1,%2,%3};" \
        : "+f"((d)[0]), "+f"((d)[1]), "+f"((d)[2]), "+f"((d)[3]) \
        : "r"((a).x), "r"((a).y), "r"((a).z), "r"((a).w), \
          "r"((uint32_t)((b) & 0xFFFFFFFFull)), "r"((uint32_t)((b) >> 32)))

// -------------------------- CSR build --------------------------------------
__global__ void k_detect(const void* ei, int slots64) {
    __shared__ int nonzero;
    if (threadIdx.x == 0) nonzero = 0;
    __syncthreads();
    const int* w = (const int*)ei;
    int slots = slots64 < 4096 ? slots64 : 4096;
    int any = 0;
    for (int i = threadIdx.x; i < slots; i += blockDim.x)
        if (w[2 * i + 1] != 0) any = 1;
    if (any) atomicOr(&nonzero, 1);
    __syncthreads();
    if (threadIdx.x == 0) g_is64 = (nonzero == 0) ? 1 : 0;
}

__global__ void k_zero_cnt(int N) {
    int i = blockIdx.x * blockDim.x + threadIdx.x;
    if (i < N) g_cnt[i] = 0;
}

__global__ void k_count(const void* ei, int E) {
    int e = blockIdx.x * blockDim.x + threadIdx.x;
    if (e >= E) return;
    int d = eidx(ei, (long long)E + e, g_is64);
    atomicAdd(&g_cnt[d], 1);
}

__global__ void k_scan1(int N) {
    __shared__ int s[256];
    int b = blockIdx.x, t = threadIdx.x;
    int base = b * 2048 + t * 8;
    int v[8];
    int sum = 0;
#pragma unroll
    for (int j = 0; j < 8; j++) {
        int i = base + j;
        v[j] = (i < N) ? g_cnt[i] : 0;
        sum += v[j];
    }
    s[t] = sum;
    __syncthreads();
    for (int off = 1; off < 256; off <<= 1) {
        int x = (t >= off) ? s[t - off] : 0;
        __syncthreads();
        s[t] += x;
        __syncthreads();
    }
    int ex = s[t] - sum;
#pragma unroll
    for (int j = 0; j < 8; j++) {
        int i = base + j;
        if (i < N) g_rowptr[i] = ex;
        ex += v[j];
    }
    if (t == 255) g_bsum[b] = s[255];
}

__global__ void k_scan2(int nb, int N) {
    __shared__ int s[64];
    int t = threadIdx.x;
    int v = (t < nb) ? g_bsum[t] : 0;
    s[t] = v;
    __syncthreads();
    for (int off = 1; off < 64; off <<= 1) {
        int x = (t >= off) ? s[t - off] : 0;
        __syncthreads();
        s[t] += x;
        __syncthreads();
    }
    if (t < nb) g_boff[t] = s[t] - v;
    if (t == 63) g_rowptr[N] = s[63];
}

__global__ void k_scan3(int N) {
    int i = blockIdx.x * blockDim.x + threadIdx.x;
    if (i >= N) return;
    int rp = g_rowptr[i] + g_boff[i >> 11];
    g_rowptr[i] = rp;
    g_cursor[i] = rp;
    int c = g_cnt[i];
    g_dinv[i] = 1.0f / (float)(c > 1 ? c : 1);
}

__global__ void k_fill(const void* ei, int E) {
    int e = blockIdx.x * blockDim.x + threadIdx.x;
    if (e >= E) return;
    int is64 = g_is64;
    int src = eidx(ei, e, is64);
    int dst = eidx(ei, (long long)E + e, is64);
    int pos = atomicAdd(&g_cursor[dst], 1);
    g_col[pos] = src;
}

// ---- weight prep: tf32 convert + pack into m16n8k8 B-fragment order -------
// Source W is [k=128][c=128] row-major. B-frag (col-major n8k8):
//   b0: k = lane&3,      n = lane>>2
//   b1: k = (lane&3)+4,  n = lane>>2
// Layout per matrix: [p(2)][s(8)][nb(16)][lane(32)][reg(2)] u32.
__global__ void k_wprep(const float* __restrict__ W1l, const float* __restrict__ W1r,
                        const float* __restrict__ W2l, const float* __restrict__ W2r) {
    int i = blockIdx.x * blockDim.x + threadIdx.x;
    if (i >= 4 * 16384) return;
    int m = i >> 14, e = i & 16383;
    int k = e >> 7, c = e & 127;
    const float* Ws[4] = {W1l, W1r, W2l, W2r};
    uint32_t v = f2tf32(__ldg(Ws[m] + e));
    int p = k >> 6, s = (k >> 3) & 7, kk = k & 7;
    int nb = c >> 3;
    int lane = ((c & 7) << 2) | (kk & 3);
    int reg = kk >> 2;
    g_wtf[(((m * 2 + p) * 8 + s) * 16 + nb) * 64 + lane * 2 + reg] = v;
}

// ------------- mean aggregation (fp32, warp per node, x4 unroll) -----------
__global__ void k_agg(const float* __restrict__ hin, float* __restrict__ out, int N) {
    int warp = (blockIdx.x * blockDim.x + threadIdx.x) >> 5;
    int lane = threadIdx.x & 31;
    if (warp >= N) return;
    int beg = g_rowptr[warp];
    int end = g_rowptr[warp + 1];
    const float4* h4 = (const float4*)hin;
    float4 a0 = make_float4(0.f, 0.f, 0.f, 0.f);
    float4 a1 = a0;
    int j = beg;
    for (; j + 3 < end; j += 4) {
        int s0 = __ldg(&g_col[j]);
        int s1 = __ldg(&g_col[j + 1]);
        int s2 = __ldg(&g_col[j + 2]);
        int s3 = __ldg(&g_col[j + 3]);
        float4 v0 = __ldg(&h4[(long long)s0 * 32 + lane]);
        float4 v1 = __ldg(&h4[(long long)s1 * 32 + lane]);
        float4 v2 = __ldg(&h4[(long long)s2 * 32 + lane]);
        float4 v3 = __ldg(&h4[(long long)s3 * 32 + lane]);
        a0.x += v0.x + v2.x; a0.y += v0.y + v2.y; a0.z += v0.z + v2.z; a0.w += v0.w + v2.w;
        a1.x += v1.x + v3.x; a1.y += v1.y + v3.y; a1.z += v1.z + v3.z; a1.w += v1.w + v3.w;
    }
    for (; j < end; j++) {
        int s = __ldg(&g_col[j]);
        float4 v = __ldg(&h4[(long long)s * 32 + lane]);
        a0.x += v.x; a0.y += v.y; a0.z += v.z; a0.w += v.w;
    }
    float dv = g_dinv[warp];
    float4 o;
    o.x = (a0.x + a1.x) * dv;
    o.y = (a0.y + a1.y) * dv;
    o.z = (a0.z + a1.z) * dv;
    o.w = (a0.w + a1.w) * dv;
    ((float4*)out)[(long long)warp * 32 + lane] = o;
}

// ------------------- tf32 tensor-core fused SAGE GEMM ----------------------
// out[128 rows x 128 cols] = A@Wl + X@Wr + b (+leaky).
// 8 warps: warp_m = wid>>1 (rows 32*warp_m), warp_n = wid&1 (cols 64*warp_n).
// A staged in smem pre-permuted to m16n8k8 A-fragment order (LDS.128/frag);
// B-frags read straight from fragment-packed global weights (L1-hot).
__global__ void __launch_bounds__(256, 2)
k_gemm(const float* __restrict__ A, const float* __restrict__ X,
       const unsigned long long* __restrict__ wA,
       const unsigned long long* __restrict__ wX,
       const float* __restrict__ bias, float* __restrict__ out,
       int N, int leaky) {
    // A fragment store: [sidx(8)][mb(8)][lane(32)][reg(4)] u32 = 32KB
    __shared__ uint32_t sA[8192];
    int tid = threadIdx.x;
    int lane = tid & 31;
    int wid = tid >> 5;
    int warp_n = wid & 1;
    int warp_m = wid >> 1;
    long long row0 = (long long)blockIdx.x * 128;

    float acc[2][8][4];
#pragma unroll
    for (int mi = 0; mi < 2; mi++)
#pragma unroll
        for (int ni = 0; ni < 8; ni++)
#pragma unroll
            for (int r = 0; r < 4; r++) acc[mi][ni][r] = 0.f;

#pragma unroll 1
    for (int seg = 0; seg < 2; seg++) {
        const float* src = seg ? X : A;
        const unsigned long long* gw = seg ? wX : wA;
#pragma unroll 1
        for (int p = 0; p < 2; p++) {
            __syncthreads();   // previous compute done before overwrite
            // stage 128 rows x 64 k (k-half p) into fragment order
#pragma unroll
            for (int it = 0; it < 8; it++) {
                int i = tid + it * 256;        // 2048 float4 slots
                int r = i >> 4, kq = i & 15;
                long long grow = row0 + r;
                float4 v = make_float4(0.f, 0.f, 0.f, 0.f);
                if (grow < N)
                    v = __ldg((const float4*)src + grow * 32 + p * 16 + kq);
                int k0 = kq * 4;
                int g = r & 15, mb = r >> 4;
                int sidx = k0 >> 3;
                int reg = ((g >> 3) & 1) | (((k0 & 7) >> 2) << 1);
                uint32_t base = (((sidx * 8 + mb) * 32 + ((g & 7) << 2)) << 2) + reg;
                sA[base]      = f2tf32(v.x);
                sA[base + 4]  = f2tf32(v.y);
                sA[base + 8]  = f2tf32(v.z);
                sA[base + 12] = f2tf32(v.w);
            }
            __syncthreads();

            // compute: 8 k8 steps
#pragma unroll
            for (int s = 0; s < 8; s++) {
                uint4 a0 = *(const uint4*)&sA[((s * 8 + warp_m * 2 + 0) * 32 + lane) * 4];
                uint4 a1 = *(const uint4*)&sA[((s * 8 + warp_m * 2 + 1) * 32 + lane) * 4];
                unsigned long long bv[8];
#pragma unroll
                for (int nb = 0; nb < 8; nb++)
                    bv[nb] = __ldg(gw + (((p * 8 + s) * 16 + warp_n * 8 + nb) * 32 + lane));
#pragma unroll
                for (int nb = 0; nb < 8; nb++) {
                    MMA_TF32(acc[0][nb], a0, bv[nb]);
                    MMA_TF32(acc[1][nb], a1, bv[nb]);
                }
            }
        }
    }

    // epilogue: bias + optional leaky, direct float2 stores
    int g4 = lane >> 2, t4 = lane & 3;
#pragma unroll
    for (int mi = 0; mi < 2; mi++) {
#pragma unroll
        for (int ni = 0; ni < 8; ni++) {
            int col = warp_n * 64 + ni * 8 + t4 * 2;
            float b0 = __ldg(bias + col);
            float b1 = __ldg(bias + col + 1);
            long long r0 = row0 + warp_m * 32 + mi * 16 + g4;
            float v0 = acc[mi][ni][0] + b0;
            float v1 = acc[mi][ni][1] + b1;
            float v2 = acc[mi][ni][2] + b0;
            float v3 = acc[mi][ni][3] + b1;
            if (leaky) {
                v0 = v0 >= 0.f ? v0 : 0.2f * v0;
                v1 = v1 >= 0.f ? v1 : 0.2f * v1;
                v2 = v2 >= 0.f ? v2 : 0.2f * v2;
                v3 = v3 >= 0.f ? v3 : 0.2f * v3;
            }
            if (r0 < N) {
                float2 o; o.x = v0; o.y = v1;
                *(float2*)(out + r0 * 128 + col) = o;
            }
            if (r0 + 8 < N) {
                float2 o; o.x = v2; o.y = v3;
                *(float2*)(out + (r0 + 8) * 128 + col) = o;
            }
        }
    }
}

// ------------------- link prediction dot ------------------------------------
__global__ void k_dot(const float* __restrict__ h, const void* __restrict__ eli,
                      float* __restrict__ out, int L) {
    int warp = (blockIdx.x * blockDim.x + threadIdx.x) >> 5;
    int lane = threadIdx.x & 31;
    if (warp >= L) return;
    int is64 = g_is64;
    int a = eidx(eli, warp, is64);
    int b = eidx(eli, (long long)L + warp, is64);
    const float4* h4 = (const float4*)h;
    float4 va = __ldg(&h4[(long long)a * 32 + lane]);
    float4 vb = __ldg(&h4[(long long)b * 32 + lane]);
    float s = va.x * vb.x + va.y * vb.y + va.z * vb.z + va.w * vb.w;
#pragma unroll
    for (int o = 16; o; o >>= 1) s += __shfl_xor_sync(0xFFFFFFFFu, s, o);
    if (lane == 0) out[warp] = s;
}

extern "C" void kernel_launch(void* const* d_in, const int* in_sizes, int n_in,
                              void* d_out, int out_size) {
    const float* x   = (const float*)d_in[0];
    const void*  ei  = d_in[1];
    const void*  eli = d_in[2];
    const float* W1l = (const float*)d_in[3];
    const float* b1  = (const float*)d_in[4];
    const float* W1r = (const float*)d_in[5];
    const float* W2l = (const float*)d_in[6];
    const float* b2  = (const float*)d_in[7];
    const float* W2r = (const float*)d_in[8];
    float* out = (float*)d_out;

    int N = in_sizes[0] / 128;
    int E = in_sizes[1] / 2;
    int L = in_sizes[2] / 2;

    float *agg, *h1, *h2;
    uint32_t* wtf;
    cudaGetSymbolAddress((void**)&agg, g_agg);
    cudaGetSymbolAddress((void**)&h1,  g_h1);
    cudaGetSymbolAddress((void**)&h2,  g_h2);
    cudaGetSymbolAddress((void**)&wtf, g_wtf);

    // CSR build
    k_detect<<<1, 256>>>(ei, E);
    k_zero_cnt<<<(N + 255) / 256, 256>>>(N);
    k_count<<<(E + 255) / 256, 256>>>(ei, E);
    int nb = (N + 2047) / 2048;
    k_scan1<<<nb, 256>>>(N);
    k_scan2<<<1, 64>>>(nb, N);
    k_scan3<<<(N + 255) / 256, 256>>>(N);
    k_fill<<<(E + 255) / 256, 256>>>(ei, E);

    // weight prep (tf32 fragment pack)
    k_wprep<<<256, 256>>>(W1l, W1r, W2l, W2r);

    const unsigned long long* w1l = (const unsigned long long*)(wtf + 0 * 16384);
    const unsigned long long* w1r = (const unsigned long long*)(wtf + 1 * 16384);
    const unsigned long long* w2l = (const unsigned long long*)(wtf + 2 * 16384);
    const unsigned long long* w2r = (const unsigned long long*)(wtf + 3 * 16384);

    int aggBlocks = (N + 7) / 8;
    int gemmBlocks = (N + 127) / 128;

    // Layer 1
    k_agg<<<aggBlocks, 256>>>(x, agg, N);
    k_gemm<<<gemmBlocks, 256>>>(agg, x, w1l, w1r, b1, h1, N, 1);
    // Layer 2
    k_agg<<<aggBlocks, 256>>>(h1, agg, N);
    k_gemm<<<gemmBlocks, 256>>>(agg, h1, w2l, w2r, b2, h2, N, 0);
    // Edge dot
    k_dot<<<(L + 7) / 8, 256>>>(h2, eli, out, L);
}

// round 5
// speedup vs baseline: 2.3852x; 1.1579x over previous
#include <cuda_runtime.h>
#include <cuda_fp16.h>
#include <cstdint>

// ---------------------------------------------------------------------------
// LinkPredModel: 2-layer GraphSAGE (mean agg) + edge dot
// R5: fp16 feature pipeline. tf32 mantissa == fp16 mantissa (10 bits), so
// fp16 activations cost nothing at the GEMM and halve all gather traffic.
// Aggregation accumulates fp32; h2 stays fp32 for the final dot.
// ---------------------------------------------------------------------------

#define MAXN 100000
#define MAXE 3200000

__device__ int   g_cnt[MAXN];
__device__ int   g_rowptr[MAXN + 1];
__device__ int   g_cursor[MAXN];
__device__ float g_dinv[MAXN];
__device__ int   g_col[MAXE];
__device__ int   g_is64;
__device__ int   g_bsum[64];
__device__ int   g_boff[64];

__device__ __align__(16) __half g_xh  [(long long)MAXN * 128];
__device__ __align__(16) __half g_aggh[(long long)MAXN * 128];
__device__ __align__(16) __half g_h1h [(long long)MAXN * 128];
__device__ __align__(16) float  g_h2  [(long long)MAXN * 128];
// fragment-packed tf32 weights: [W1l, W1r, W2l, W2r] x 16384 u32 each
__device__ __align__(16) uint32_t g_wtf[4 * 16384];

// ---- index accessor: tolerate int64 or int32 edge index buffers ----------
__device__ __forceinline__ int eidx(const void* p, long long i, int is64) {
    if (is64) return (int)__ldg(((const long long*)p) + i);
    return __ldg(((const int*)p) + i);
}

__device__ __forceinline__ uint32_t f2tf32(float f) {
    uint32_t u;
    asm("cvt.rna.tf32.f32 %0, %1;" : "=r"(u) : "f"(f));
    return u;
}

#define MMA_TF32(d, a, b) \
    asm volatile("mma.sync.aligned.m16n8k8.row.col.f32.tf32.tf32.f32 " \
        "{%0,%1,%2,%3},{%4,%5,%6,%7},{%8,%9},{%0,%1,%2,%3};" \
        : "+f"((d)[0]), "+f"((d)[1]), "+f"((d)[2]), "+f"((d)[3]) \
        : "r"((a).x), "r"((a).y), "r"((a).z), "r"((a).w), \
          "r"((uint32_t)((b) & 0xFFFFFFFFull)), "r"((uint32_t)((b) >> 32)))

// -------------------------- CSR build --------------------------------------
__global__ void k_detect(const void* ei, int slots64) {
    __shared__ int nonzero;
    if (threadIdx.x == 0) nonzero = 0;
    __syncthreads();
    const int* w = (const int*)ei;
    int slots = slots64 < 4096 ? slots64 : 4096;
    int any = 0;
    for (int i = threadIdx.x; i < slots; i += blockDim.x)
        if (w[2 * i + 1] != 0) any = 1;
    if (any) atomicOr(&nonzero, 1);
    __syncthreads();
    if (threadIdx.x == 0) g_is64 = (nonzero == 0) ? 1 : 0;
}

__global__ void k_zero_cnt(int N) {
    int i = blockIdx.x * blockDim.x + threadIdx.x;
    if (i < N) g_cnt[i] = 0;
}

__global__ void k_count(const void* ei, int E) {
    int e = blockIdx.x * blockDim.x + threadIdx.x;
    if (e >= E) return;
    int d = eidx(ei, (long long)E + e, g_is64);
    atomicAdd(&g_cnt[d], 1);
}

__global__ void k_scan1(int N) {
    __shared__ int s[256];
    int b = blockIdx.x, t = threadIdx.x;
    int base = b * 2048 + t * 8;
    int v[8];
    int sum = 0;
#pragma unroll
    for (int j = 0; j < 8; j++) {
        int i = base + j;
        v[j] = (i < N) ? g_cnt[i] : 0;
        sum += v[j];
    }
    s[t] = sum;
    __syncthreads();
    for (int off = 1; off < 256; off <<= 1) {
        int x = (t >= off) ? s[t - off] : 0;
        __syncthreads();
        s[t] += x;
        __syncthreads();
    }
    int ex = s[t] - sum;
#pragma unroll
    for (int j = 0; j < 8; j++) {
        int i = base + j;
        if (i < N) g_rowptr[i] = ex;
        ex += v[j];
    }
    if (t == 255) g_bsum[b] = s[255];
}

__global__ void k_scan2(int nb, int N) {
    __shared__ int s[64];
    int t = threadIdx.x;
    int v = (t < nb) ? g_bsum[t] : 0;
    s[t] = v;
    __syncthreads();
    for (int off = 1; off < 64; off <<= 1) {
        int x = (t >= off) ? s[t - off] : 0;
        __syncthreads();
        s[t] += x;
        __syncthreads();
    }
    if (t < nb) g_boff[t] = s[t] - v;
    if (t == 63) g_rowptr[N] = s[63];
}

__global__ void k_scan3(int N) {
    int i = blockIdx.x * blockDim.x + threadIdx.x;
    if (i >= N) return;
    int rp = g_rowptr[i] + g_boff[i >> 11];
    g_rowptr[i] = rp;
    g_cursor[i] = rp;
    int c = g_cnt[i];
    g_dinv[i] = 1.0f / (float)(c > 1 ? c : 1);
}

__global__ void k_fill(const void* ei, int E) {
    int e = blockIdx.x * blockDim.x + threadIdx.x;
    if (e >= E) return;
    int is64 = g_is64;
    int src = eidx(ei, e, is64);
    int dst = eidx(ei, (long long)E + e, is64);
    int pos = atomicAdd(&g_cursor[dst], 1);
    g_col[pos] = src;
}

// ---- weight prep: tf32 convert + pack into m16n8k8 B-fragment order -------
// Layout per matrix: [p(2)][s(8)][nb(16)][lane(32)][reg(2)] u32.
__global__ void k_wprep(const float* __restrict__ W1l, const float* __restrict__ W1r,
                        const float* __restrict__ W2l, const float* __restrict__ W2r) {
    int i = blockIdx.x * blockDim.x + threadIdx.x;
    if (i >= 4 * 16384) return;
    int m = i >> 14, e = i & 16383;
    int k = e >> 7, c = e & 127;
    const float* Ws[4] = {W1l, W1r, W2l, W2r};
    uint32_t v = f2tf32(__ldg(Ws[m] + e));
    int p = k >> 6, s = (k >> 3) & 7, kk = k & 7;
    int nb = c >> 3;
    int lane = ((c & 7) << 2) | (kk & 3);
    int reg = kk >> 2;
    g_wtf[(((m * 2 + p) * 8 + s) * 16 + nb) * 64 + lane * 2 + reg] = v;
}

// ---- fp32 -> fp16 convert (x features) -------------------------------------
__global__ void k_half(const float* __restrict__ x, __half* __restrict__ o, int n4) {
    int i = blockIdx.x * blockDim.x + threadIdx.x;
    if (i >= n4) return;
    float4 v = __ldg((const float4*)x + i);
    __half2 h0 = __floats2half2_rn(v.x, v.y);
    __half2 h1 = __floats2half2_rn(v.z, v.w);
    uint2 ov;
    ov.x = *(uint32_t*)&h0;
    ov.y = *(uint32_t*)&h1;
    ((uint2*)o)[i] = ov;
}

// ------------- mean aggregation (fp16 gather, fp32 accumulate) -------------
// warp per node; lane owns 4 features (uint2 = 4 halves); x4 edge unroll.
__global__ void k_agg(const __half* __restrict__ hin, __half* __restrict__ out, int N) {
    int node = (blockIdx.x * blockDim.x + threadIdx.x) >> 5;
    int lane = threadIdx.x & 31;
    if (node >= N) return;
    int beg = g_rowptr[node];
    int end = g_rowptr[node + 1];
    const uint2* hp = (const uint2*)hin;   // 32 uint2 per row
    float a0 = 0.f, a1 = 0.f, a2 = 0.f, a3 = 0.f;
    float b0 = 0.f, b1 = 0.f, b2 = 0.f, b3 = 0.f;
    int j = beg;
    for (; j + 3 < end; j += 4) {
        int s0 = __ldg(&g_col[j]);
        int s1 = __ldg(&g_col[j + 1]);
        int s2 = __ldg(&g_col[j + 2]);
        int s3 = __ldg(&g_col[j + 3]);
        uint2 u0 = __ldg(&hp[(long long)s0 * 32 + lane]);
        uint2 u1 = __ldg(&hp[(long long)s1 * 32 + lane]);
        uint2 u2 = __ldg(&hp[(long long)s2 * 32 + lane]);
        uint2 u3 = __ldg(&hp[(long long)s3 * 32 + lane]);
        float2 p0 = __half22float2(*(__half2*)&u0.x);
        float2 p1 = __half22float2(*(__half2*)&u0.y);
        float2 q0 = __half22float2(*(__half2*)&u1.x);
        float2 q1 = __half22float2(*(__half2*)&u1.y);
        float2 r0 = __half22float2(*(__half2*)&u2.x);
        float2 r1 = __half22float2(*(__half2*)&u2.y);
        float2 t0 = __half22float2(*(__half2*)&u3.x);
        float2 t1 = __half22float2(*(__half2*)&u3.y);
        a0 += p0.x + r0.x; a1 += p0.y + r0.y; a2 += p1.x + r1.x; a3 += p1.y + r1.y;
        b0 += q0.x + t0.x; b1 += q0.y + t0.y; b2 += q1.x + t1.x; b3 += q1.y + t1.y;
    }
    for (; j < end; j++) {
        int s = __ldg(&g_col[j]);
        uint2 u = __ldg(&hp[(long long)s * 32 + lane]);
        float2 p0 = __half22float2(*(__half2*)&u.x);
        float2 p1 = __half22float2(*(__half2*)&u.y);
        a0 += p0.x; a1 += p0.y; a2 += p1.x; a3 += p1.y;
    }
    float dv = g_dinv[node];
    float m0 = (a0 + b0) * dv, m1 = (a1 + b1) * dv;
    float m2 = (a2 + b2) * dv, m3 = (a3 + b3) * dv;
    __half2 o01 = __floats2half2_rn(m0, m1);
    __half2 o23 = __floats2half2_rn(m2, m3);
    uint2 ov;
    ov.x = *(uint32_t*)&o01;
    ov.y = *(uint32_t*)&o23;
    ((uint2*)out)[(long long)node * 32 + lane] = ov;
}

// ------------------- tf32 tensor-core fused SAGE GEMM ----------------------
// out[128 x 128] = A@Wl + X@Wr + b (+leaky). A, X are fp16 (exact into tf32).
// 8 warps: warp_m = wid>>1, warp_n = wid&1. A staged in smem in m16n8k8
// A-fragment order; B-frags from fragment-packed global weights (L1-hot).
__global__ void __launch_bounds__(256, 2)
k_gemm(const __half* __restrict__ A, const __half* __restrict__ X,
       const unsigned long long* __restrict__ wA,
       const unsigned long long* __restrict__ wX,
       const float* __restrict__ bias,
       __half* __restrict__ outH, float* __restrict__ outF,
       int N, int leaky) {
    __shared__ uint32_t sA[8192];   // [sidx(8)][mb(8)][lane(32)][reg(4)]
    int tid = threadIdx.x;
    int lane = tid & 31;
    int wid = tid >> 5;
    int warp_n = wid & 1;
    int warp_m = wid >> 1;
    long long row0 = (long long)blockIdx.x * 128;

    float acc[2][8][4];
#pragma unroll
    for (int mi = 0; mi < 2; mi++)
#pragma unroll
        for (int ni = 0; ni < 8; ni++)
#pragma unroll
            for (int r = 0; r < 4; r++) acc[mi][ni][r] = 0.f;

#pragma unroll 1
    for (int seg = 0; seg < 2; seg++) {
        const __half* src = seg ? X : A;
        const unsigned long long* gw = seg ? wX : wA;
#pragma unroll 1
        for (int p = 0; p < 2; p++) {
            __syncthreads();
            // stage 128 rows x 64 k (k-half p) into fragment order
#pragma unroll
            for (int it = 0; it < 8; it++) {
                int i = tid + it * 256;        // 2048 uint2 slots (4 halves each)
                int r = i >> 4, kq = i & 15;
                long long grow = row0 + r;
                uint2 v = make_uint2(0, 0);
                if (grow < N)
                    v = __ldg((const uint2*)src + grow * 32 + p * 16 + kq);
                float2 f01 = __half22float2(*(__half2*)&v.x);
                float2 f23 = __half22float2(*(__half2*)&v.y);
                int k0 = kq * 4;
                int g = r & 15, mb = r >> 4;
                int sidx = k0 >> 3;
                int reg = ((g >> 3) & 1) | (((k0 & 7) >> 2) << 1);
                uint32_t base = (((sidx * 8 + mb) * 32 + ((g & 7) << 2)) << 2) + reg;
                sA[base]      = f2tf32(f01.x);
                sA[base + 4]  = f2tf32(f01.y);
                sA[base + 8]  = f2tf32(f23.x);
                sA[base + 12] = f2tf32(f23.y);
            }
            __syncthreads();

            // compute: 8 k8 steps
#pragma unroll
            for (int s = 0; s < 8; s++) {
                uint4 a0 = *(const uint4*)&sA[((s * 8 + warp_m * 2 + 0) * 32 + lane) * 4];
                uint4 a1 = *(const uint4*)&sA[((s * 8 + warp_m * 2 + 1) * 32 + lane) * 4];
                unsigned long long bv[8];
#pragma unroll
                for (int nb = 0; nb < 8; nb++)
                    bv[nb] = __ldg(gw + (((p * 8 + s) * 16 + warp_n * 8 + nb) * 32 + lane));
#pragma unroll
                for (int nb = 0; nb < 8; nb++) {
                    MMA_TF32(acc[0][nb], a0, bv[nb]);
                    MMA_TF32(acc[1][nb], a1, bv[nb]);
                }
            }
        }
    }

    // epilogue: bias + optional leaky; fp16 store (layer1) or fp32 (layer2)
    int g4 = lane >> 2, t4 = lane & 3;
#pragma unroll
    for (int mi = 0; mi < 2; mi++) {
#pragma unroll
        for (int ni = 0; ni < 8; ni++) {
            int col = warp_n * 64 + ni * 8 + t4 * 2;
            float b0 = __ldg(bias + col);
            float b1 = __ldg(bias + col + 1);
            long long r0 = row0 + warp_m * 32 + mi * 16 + g4;
            float v0 = acc[mi][ni][0] + b0;
            float v1 = acc[mi][ni][1] + b1;
            float v2 = acc[mi][ni][2] + b0;
            float v3 = acc[mi][ni][3] + b1;
            if (leaky) {
                v0 = v0 >= 0.f ? v0 : 0.2f * v0;
                v1 = v1 >= 0.f ? v1 : 0.2f * v1;
                v2 = v2 >= 0.f ? v2 : 0.2f * v2;
                v3 = v3 >= 0.f ? v3 : 0.2f * v3;
            }
            if (outF) {
                if (r0 < N) {
                    float2 o; o.x = v0; o.y = v1;
                    *(float2*)(outF + r0 * 128 + col) = o;
                }
                if (r0 + 8 < N) {
                    float2 o; o.x = v2; o.y = v3;
                    *(float2*)(outF + (r0 + 8) * 128 + col) = o;
                }
            } else {
                if (r0 < N) {
                    __half2 o = __floats2half2_rn(v0, v1);
                    *(uint32_t*)(outH + r0 * 128 + col) = *(uint32_t*)&o;
                }
                if (r0 + 8 < N) {
                    __half2 o = __floats2half2_rn(v2, v3);
                    *(uint32_t*)(outH + (r0 + 8) * 128 + col) = *(uint32_t*)&o;
                }
            }
        }
    }
}

// ------------------- link prediction dot ------------------------------------
__global__ void k_dot(const float* __restrict__ h, const void* __restrict__ eli,
                      float* __restrict__ out, int L) {
    int warp = (blockIdx.x * blockDim.x + threadIdx.x) >> 5;
    int lane = threadIdx.x & 31;
    if (warp >= L) return;
    int is64 = g_is64;
    int a = eidx(eli, warp, is64);
    int b = eidx(eli, (long long)L + warp, is64);
    const float4* h4 = (const float4*)h;
    float4 va = __ldg(&h4[(long long)a * 32 + lane]);
    float4 vb = __ldg(&h4[(long long)b * 32 + lane]);
    float s = va.x * vb.x + va.y * vb.y + va.z * vb.z + va.w * vb.w;
#pragma unroll
    for (int o = 16; o; o >>= 1) s += __shfl_xor_sync(0xFFFFFFFFu, s, o);
    if (lane == 0) out[warp] = s;
}

extern "C" void kernel_launch(void* const* d_in, const int* in_sizes, int n_in,
                              void* d_out, int out_size) {
    const float* x   = (const float*)d_in[0];
    const void*  ei  = d_in[1];
    const void*  eli = d_in[2];
    const float* W1l = (const float*)d_in[3];
    const float* b1  = (const float*)d_in[4];
    const float* W1r = (const float*)d_in[5];
    const float* W2l = (const float*)d_in[6];
    const float* b2  = (const float*)d_in[7];
    const float* W2r = (const float*)d_in[8];
    float* out = (float*)d_out;

    int N = in_sizes[0] / 128;
    int E = in_sizes[1] / 2;
    int L = in_sizes[2] / 2;

    __half *xh, *aggh, *h1h;
    float* h2;
    uint32_t* wtf;
    cudaGetSymbolAddress((void**)&xh,   g_xh);
    cudaGetSymbolAddress((void**)&aggh, g_aggh);
    cudaGetSymbolAddress((void**)&h1h,  g_h1h);
    cudaGetSymbolAddress((void**)&h2,   g_h2);
    cudaGetSymbolAddress((void**)&wtf,  g_wtf);

    // CSR build
    k_detect<<<1, 256>>>(ei, E);
    k_zero_cnt<<<(N + 255) / 256, 256>>>(N);
    k_count<<<(E + 255) / 256, 256>>>(ei, E);
    int nb = (N + 2047) / 2048;
    k_scan1<<<nb, 256>>>(N);
    k_scan2<<<1, 64>>>(nb, N);
    k_scan3<<<(N + 255) / 256, 256>>>(N);
    k_fill<<<(E + 255) / 256, 256>>>(ei, E);

    // weight + feature prep
    k_wprep<<<256, 256>>>(W1l, W1r, W2l, W2r);
    k_half<<<(N * 32 + 255) / 256, 256>>>(x, xh, N * 32);

    const unsigned long long* w1l = (const unsigned long long*)(wtf + 0 * 16384);
    const unsigned long long* w1r = (const unsigned long long*)(wtf + 1 * 16384);
    const unsigned long long* w2l = (const unsigned long long*)(wtf + 2 * 16384);
    const unsigned long long* w2r = (const unsigned long long*)(wtf + 3 * 16384);

    int aggBlocks = (N + 7) / 8;
    int gemmBlocks = (N + 127) / 128;

    // Layer 1
    k_agg<<<aggBlocks, 256>>>(xh, aggh, N);
    k_gemm<<<gemmBlocks, 256>>>(aggh, xh, w1l, w1r, b1, h1h, (float*)0, N, 1);
    // Layer 2
    k_agg<<<aggBlocks, 256>>>(h1h, aggh, N);
    k_gemm<<<gemmBlocks, 256>>>(aggh, h1h, w2l, w2r, b2, (__half*)0, h2, N, 0);
    // Edge dot
    k_dot<<<(L + 7) / 8, 256>>>(h2, eli, out, L);
}